// round 2
// baseline (speedup 1.0000x reference)
#include <cuda_runtime.h>
#include <cuda_bf16.h>
#include <math.h>

#define B_ 64
#define W_ 4096
#define H_ 128
#define I_ 128
#define CHUNKS 8
#define TPB (W_ / CHUNKS)          // 512 tokens per block
#define WARPS 8
#define ROWS_PER_WARP (TPB / WARPS) // 64 rows per warp

// Partial online-softmax results per (batch, chunk)
__device__ float g_pm[B_ * CHUNKS];
__device__ float g_pl[B_ * CHUNKS];
__device__ float g_pacc[B_ * CHUNKS * H_];

__device__ __forceinline__ float warp_sum(float v) {
    #pragma unroll
    for (int o = 16; o; o >>= 1) v += __shfl_xor_sync(0xffffffffu, v, o);
    return v;
}

// ---------------------------------------------------------------------------
// Phase 1: fused score + online-softmax weighted sum over encoder_output.
// Logit of token w is: 0 for w==0, score(row w-1)+bias for w>=1,
// where score(row) = enc[b,row,:] . att_W[0:H] and
// bias = sum_h h0[1,b,h]*c0[1,b,h]*att_W[H+h] + att_b.
// Each warp processes a contiguous range of rows, computing the row's dot
// product (used as next row's logit) and accumulating exp(logit)*row online.
// ---------------------------------------------------------------------------
__global__ __launch_bounds__(256, 4)
void attn_partial_kernel(const float* __restrict__ enc,
                         const float* __restrict__ h0,
                         const float* __restrict__ c0,
                         const float* __restrict__ attW,
                         const float* __restrict__ attB)
{
    const int c    = blockIdx.x;
    const int b    = blockIdx.y;
    const int tid  = threadIdx.x;
    const int warp = tid >> 5;
    const int lane = tid & 31;

    __shared__ float s_red[WARPS];
    __shared__ float s_bias;
    __shared__ float s_m[WARPS], s_l[WARPS];
    __shared__ float s_acc[WARPS][H_];

    // ---- per-batch bias (cheap, recomputed by every block) ----
    float part = 0.f;
    if (tid < H_) {
        float hs = h0[(1 * B_ + b) * H_ + tid];
        float cs = c0[(1 * B_ + b) * H_ + tid];
        part = hs * cs * attW[H_ + tid];
    }
    part = warp_sum(part);
    if (lane == 0) s_red[warp] = part;
    __syncthreads();
    if (tid == 0) {
        float s = 0.f;
        #pragma unroll
        for (int w = 0; w < WARPS; w++) s += s_red[w];
        s_bias = s + attB[0];
    }
    __syncthreads();
    const float bias = s_bias;

    // encoder-attention weight, 4 consecutive values per lane
    const float4 wa = *reinterpret_cast<const float4*>(attW + lane * 4);

    const int rowStart = c * TPB + warp * ROWS_PER_WARP;
    const float* encb = enc + (size_t)b * W_ * H_;

    // prologue: logit feeding the first row of this warp's range
    float prevLogit;
    if (rowStart == 0) {
        prevLogit = 0.0f;                 // logit of token 0 is exactly 0
    } else {
        float4 v = *reinterpret_cast<const float4*>(
            encb + (size_t)(rowStart - 1) * H_ + lane * 4);
        float d = v.x * wa.x + v.y * wa.y + v.z * wa.z + v.w * wa.w;
        d = warp_sum(d);
        prevLogit = d + bias;
    }

    float m = -1e30f, l = 0.f;
    float ax = 0.f, ay = 0.f, az = 0.f, aw = 0.f;

    const float* rp = encb + (size_t)rowStart * H_ + lane * 4;
    #pragma unroll 4
    for (int r = 0; r < ROWS_PER_WARP; r++) {
        const float4 v = *reinterpret_cast<const float4*>(rp);
        rp += H_;
        // this row's score (becomes the NEXT row's logit)
        float d = v.x * wa.x + v.y * wa.y + v.z * wa.z + v.w * wa.w;
        d = warp_sum(d);
        const float logit = prevLogit;
        prevLogit = d + bias;
        // online softmax update
        const float mNew = fmaxf(m, logit);
        const float corr = __expf(m - mNew);
        const float p    = __expf(logit - mNew);
        l  = l * corr + p;
        ax = ax * corr + p * v.x;
        ay = ay * corr + p * v.y;
        az = az * corr + p * v.z;
        aw = aw * corr + p * v.w;
        m = mNew;
    }

    if (lane == 0) { s_m[warp] = m; s_l[warp] = l; }
    s_acc[warp][lane * 4 + 0] = ax;
    s_acc[warp][lane * 4 + 1] = ay;
    s_acc[warp][lane * 4 + 2] = az;
    s_acc[warp][lane * 4 + 3] = aw;
    __syncthreads();

    // block combine: 8 warp-partials -> one chunk-partial
    if (tid < H_) {
        float M = s_m[0];
        #pragma unroll
        for (int w = 1; w < WARPS; w++) M = fmaxf(M, s_m[w]);
        float L = 0.f, A = 0.f;
        #pragma unroll
        for (int w = 0; w < WARPS; w++) {
            const float e = __expf(s_m[w] - M);
            L += s_l[w] * e;
            A += s_acc[w][tid] * e;
        }
        const int pi = b * CHUNKS + c;
        g_pacc[pi * H_ + tid] = A;
        if (tid == 0) { g_pm[pi] = M; g_pl[pi] = L; }
    }
}

// ---------------------------------------------------------------------------
// Phase 2: combine chunk partials -> context x; xin projection; two LSTM
// cells; write output. One block per batch row, 256 threads (8 warps).
// out layout: [h2 (B,H)] [h1 (B,H)] [h2 (B,H)] [c1 (B,H)] [c2 (B,H)]
// ---------------------------------------------------------------------------
__device__ __forceinline__ float sigm(float x) { return 1.0f / (1.0f + expf(-x)); }

__global__ __launch_bounds__(256, 4)
void decode_tail_kernel(const float* __restrict__ input,
                        const float* __restrict__ h0,
                        const float* __restrict__ c0,
                        const float* __restrict__ inp_W,
                        const float* __restrict__ inp_b,
                        const float* __restrict__ W_ih0,
                        const float* __restrict__ W_hh0,
                        const float* __restrict__ b_ih0,
                        const float* __restrict__ b_hh0,
                        const float* __restrict__ W_ih1,
                        const float* __restrict__ W_hh1,
                        const float* __restrict__ b_ih1,
                        const float* __restrict__ b_hh1,
                        float* __restrict__ out)
{
    const int b    = blockIdx.x;
    const int tid  = threadIdx.x;
    const int warp = tid >> 5;
    const int lane = tid & 31;

    __shared__ float s_xcat[H_ + I_];  // [x | input]
    __shared__ float s_xin[I_];
    __shared__ float s_hprev[H_];
    __shared__ float s_g[4 * H_];
    __shared__ float s_h1[H_];

    // combine CHUNKS partials into context vector x
    if (tid < H_) {
        float M = g_pm[b * CHUNKS + 0];
        #pragma unroll
        for (int cc = 1; cc < CHUNKS; cc++) M = fmaxf(M, g_pm[b * CHUNKS + cc]);
        float L = 0.f, A = 0.f;
        #pragma unroll
        for (int cc = 0; cc < CHUNKS; cc++) {
            const float e = __expf(g_pm[b * CHUNKS + cc] - M);
            L += g_pl[b * CHUNKS + cc] * e;
            A += g_pacc[(b * CHUNKS + cc) * H_ + tid] * e;
        }
        s_xcat[tid] = A / L;
        s_hprev[tid] = h0[(0 * B_ + b) * H_ + tid];   // layer-0 h state
    } else {
        s_xcat[tid] = input[b * I_ + (tid - H_)];
    }
    __syncthreads();

    // xin[j] = xcat . inp_W[j,:] + inp_b[j]   (K = 256)
    for (int j = warp; j < I_; j += WARPS) {
        const float* wr = inp_W + j * (H_ + I_);
        float s = 0.f;
        #pragma unroll
        for (int k = lane; k < H_ + I_; k += 32) s += wr[k] * s_xcat[k];
        s = warp_sum(s);
        if (lane == 0) s_xin[j] = s + inp_b[j];
    }
    __syncthreads();

    // ---- LSTM cell 0: gates = xin @ W_ih0.T + h0[0] @ W_hh0.T + b ----
    for (int j = warp; j < 4 * H_; j += WARPS) {
        const float* wi = W_ih0 + j * I_;
        const float* wh = W_hh0 + j * H_;
        float s = 0.f;
        #pragma unroll
        for (int k = lane; k < H_; k += 32)
            s += wi[k] * s_xin[k] + wh[k] * s_hprev[k];
        s = warp_sum(s);
        if (lane == 0) s_g[j] = s + b_ih0[j] + b_hh0[j];
    }
    __syncthreads();

    if (tid < H_) {
        const float gi = s_g[tid];
        const float gf = s_g[H_ + tid];
        const float gg = s_g[2 * H_ + tid];
        const float go = s_g[3 * H_ + tid];
        const float cp = c0[(0 * B_ + b) * H_ + tid];
        const float c1 = sigm(gf) * cp + sigm(gi) * tanhf(gg);
        const float h1 = sigm(go) * tanhf(c1);
        s_h1[tid] = h1;
        out[1 * B_ * H_ + b * H_ + tid] = h1;   // h stack layer 0
        out[3 * B_ * H_ + b * H_ + tid] = c1;   // c stack layer 0
    }
    __syncthreads();

    // load layer-1 h state
    if (tid < H_) s_hprev[tid] = h0[(1 * B_ + b) * H_ + tid];
    __syncthreads();

    // ---- LSTM cell 1: gates = h1 @ W_ih1.T + h0[1] @ W_hh1.T + b ----
    for (int j = warp; j < 4 * H_; j += WARPS) {
        const float* wi = W_ih1 + j * H_;
        const float* wh = W_hh1 + j * H_;
        float s = 0.f;
        #pragma unroll
        for (int k = lane; k < H_; k += 32)
            s += wi[k] * s_h1[k] + wh[k] * s_hprev[k];
        s = warp_sum(s);
        if (lane == 0) s_g[j] = s + b_ih1[j] + b_hh1[j];
    }
    __syncthreads();

    if (tid < H_) {
        const float gi = s_g[tid];
        const float gf = s_g[H_ + tid];
        const float gg = s_g[2 * H_ + tid];
        const float go = s_g[3 * H_ + tid];
        const float cp = c0[(1 * B_ + b) * H_ + tid];
        const float c2 = sigm(gf) * cp + sigm(gi) * tanhf(gg);
        const float h2 = sigm(go) * tanhf(c2);
        out[0 * B_ * H_ + b * H_ + tid] = h2;   // output (= h2)
        out[2 * B_ * H_ + b * H_ + tid] = h2;   // h stack layer 1
        out[4 * B_ * H_ + b * H_ + tid] = c2;   // c stack layer 1
    }
}

extern "C" void kernel_launch(void* const* d_in, const int* in_sizes, int n_in,
                              void* d_out, int out_size) {
    const float* input  = (const float*)d_in[0];
    const float* h0     = (const float*)d_in[1];
    const float* c0     = (const float*)d_in[2];
    const float* enc    = (const float*)d_in[3];
    const float* attW   = (const float*)d_in[4];
    const float* attB   = (const float*)d_in[5];
    const float* inp_W  = (const float*)d_in[6];
    const float* inp_b  = (const float*)d_in[7];
    const float* W_ih0  = (const float*)d_in[8];
    const float* W_hh0  = (const float*)d_in[9];
    const float* b_ih0  = (const float*)d_in[10];
    const float* b_hh0  = (const float*)d_in[11];
    const float* W_ih1  = (const float*)d_in[12];
    const float* W_hh1  = (const float*)d_in[13];
    const float* b_ih1  = (const float*)d_in[14];
    const float* b_hh1  = (const float*)d_in[15];
    float* out = (float*)d_out;

    dim3 grid1(CHUNKS, B_);
    attn_partial_kernel<<<grid1, 256>>>(enc, h0, c0, attW, attB);
    decode_tail_kernel<<<B_, 256>>>(input, h0, c0, inp_W, inp_b,
                                    W_ih0, W_hh0, b_ih0, b_hh0,
                                    W_ih1, W_hh1, b_ih1, b_hh1, out);
}

// round 3
// speedup vs baseline: 1.9604x; 1.9604x over previous
#include <cuda_runtime.h>
#include <cuda_bf16.h>
#include <math.h>

#define B_ 64
#define W_ 4096
#define H_ 128
#define I_ 128
#define CHUNKS 8
#define TPB (W_ / CHUNKS)          // 512 tokens per block
#define WARPS 8
#define ROWS_PER_WARP (TPB / WARPS) // 64 rows per warp

// Partial online-softmax results per (batch, chunk)
__device__ float g_pm[B_ * CHUNKS];
__device__ float g_pl[B_ * CHUNKS];
__device__ float g_pacc[B_ * CHUNKS * H_];

// Transposed activations: [k][b] so that warp lanes (= b) hit one 128B line
__device__ float g_xcatT[(H_ + I_) * B_];  // context | input, 256 x 64
__device__ float g_xinT[I_ * B_];          // 128 x 64
__device__ float g_h1T[H_ * B_];           // 128 x 64
__device__ float g_h0T0[H_ * B_];          // h0 layer 0 transposed
__device__ float g_h0T1[H_ * B_];          // h0 layer 1 transposed

__device__ __forceinline__ float warp_sum(float v) {
    #pragma unroll
    for (int o = 16; o; o >>= 1) v += __shfl_xor_sync(0xffffffffu, v, o);
    return v;
}

__device__ __forceinline__ float sigm(float x) { return 1.0f / (1.0f + expf(-x)); }

// ---------------------------------------------------------------------------
// Phase 1: fused score + online-softmax weighted sum over encoder_output.
// Logit of token w: 0 for w==0, score(row w-1)+bias for w>=1.
// ---------------------------------------------------------------------------
__global__ __launch_bounds__(256, 4)
void attn_partial_kernel(const float* __restrict__ enc,
                         const float* __restrict__ h0,
                         const float* __restrict__ c0,
                         const float* __restrict__ attW,
                         const float* __restrict__ attB)
{
    const int c    = blockIdx.x;
    const int b    = blockIdx.y;
    const int tid  = threadIdx.x;
    const int warp = tid >> 5;
    const int lane = tid & 31;

    __shared__ float s_red[WARPS];
    __shared__ float s_bias;
    __shared__ float s_m[WARPS], s_l[WARPS];
    __shared__ float s_acc[WARPS][H_];

    // per-batch bias
    float part = 0.f;
    if (tid < H_) {
        float hs = h0[(1 * B_ + b) * H_ + tid];
        float cs = c0[(1 * B_ + b) * H_ + tid];
        part = hs * cs * attW[H_ + tid];
    }
    part = warp_sum(part);
    if (lane == 0) s_red[warp] = part;
    __syncthreads();
    if (tid == 0) {
        float s = 0.f;
        #pragma unroll
        for (int w = 0; w < WARPS; w++) s += s_red[w];
        s_bias = s + attB[0];
    }
    __syncthreads();
    const float bias = s_bias;

    const float4 wa = *reinterpret_cast<const float4*>(attW + lane * 4);

    const int rowStart = c * TPB + warp * ROWS_PER_WARP;
    const float* encb = enc + (size_t)b * W_ * H_;

    float prevLogit;
    if (rowStart == 0) {
        prevLogit = 0.0f;
    } else {
        float4 v = *reinterpret_cast<const float4*>(
            encb + (size_t)(rowStart - 1) * H_ + lane * 4);
        float d = v.x * wa.x + v.y * wa.y + v.z * wa.z + v.w * wa.w;
        d = warp_sum(d);
        prevLogit = d + bias;
    }

    float m = -1e30f, l = 0.f;
    float ax = 0.f, ay = 0.f, az = 0.f, aw = 0.f;

    const float* rp = encb + (size_t)rowStart * H_ + lane * 4;
    #pragma unroll 4
    for (int r = 0; r < ROWS_PER_WARP; r++) {
        const float4 v = *reinterpret_cast<const float4*>(rp);
        rp += H_;
        float d = v.x * wa.x + v.y * wa.y + v.z * wa.z + v.w * wa.w;
        d = warp_sum(d);
        const float logit = prevLogit;
        prevLogit = d + bias;
        const float mNew = fmaxf(m, logit);
        const float corr = __expf(m - mNew);
        const float p    = __expf(logit - mNew);
        l  = l * corr + p;
        ax = ax * corr + p * v.x;
        ay = ay * corr + p * v.y;
        az = az * corr + p * v.z;
        aw = aw * corr + p * v.w;
        m = mNew;
    }

    if (lane == 0) { s_m[warp] = m; s_l[warp] = l; }
    s_acc[warp][lane * 4 + 0] = ax;
    s_acc[warp][lane * 4 + 1] = ay;
    s_acc[warp][lane * 4 + 2] = az;
    s_acc[warp][lane * 4 + 3] = aw;
    __syncthreads();

    if (tid < H_) {
        float M = s_m[0];
        #pragma unroll
        for (int w = 1; w < WARPS; w++) M = fmaxf(M, s_m[w]);
        float L = 0.f, A = 0.f;
        #pragma unroll
        for (int w = 0; w < WARPS; w++) {
            const float e = __expf(s_m[w] - M);
            L += s_l[w] * e;
            A += s_acc[w][tid] * e;
        }
        const int pi = b * CHUNKS + c;
        g_pacc[pi * H_ + tid] = A;
        if (tid == 0) { g_pm[pi] = M; g_pl[pi] = L; }
    }
}

// ---------------------------------------------------------------------------
// K2: combine chunk partials -> context, build transposed activations.
// grid = B_ blocks (b), 256 threads (k over [0,256)).
// ---------------------------------------------------------------------------
__global__ __launch_bounds__(256)
void combine_kernel(const float* __restrict__ input,
                    const float* __restrict__ h0)
{
    const int b = blockIdx.x;
    const int k = threadIdx.x;

    if (k < H_) {
        float M = g_pm[b * CHUNKS + 0];
        #pragma unroll
        for (int cc = 1; cc < CHUNKS; cc++) M = fmaxf(M, g_pm[b * CHUNKS + cc]);
        float L = 0.f, A = 0.f;
        #pragma unroll
        for (int cc = 0; cc < CHUNKS; cc++) {
            const float e = __expf(g_pm[b * CHUNKS + cc] - M);
            L += g_pl[b * CHUNKS + cc] * e;
            A += g_pacc[(b * CHUNKS + cc) * H_ + k] * e;
        }
        g_xcatT[k * B_ + b] = A / L;
        g_h0T0[k * B_ + b] = h0[(0 * B_ + b) * H_ + k];
        g_h0T1[k * B_ + b] = h0[(1 * B_ + b) * H_ + k];
    } else {
        g_xcatT[k * B_ + b] = input[b * I_ + (k - H_)];
    }
}

// ---------------------------------------------------------------------------
// K3: xin[j][b] = xcat[b][:] . inp_W[j][:] + inp_b[j]   (K = 256)
// grid = 32 blocks (4 j each), 256 threads: b = tid&63, jl = tid>>6.
// Thread-per-output, weights staged in smem (uniform broadcast per warp),
// activation reads coalesced across lanes (= b). No reductions.
// ---------------------------------------------------------------------------
__global__ __launch_bounds__(256)
void xin_kernel(const float* __restrict__ inp_W,
                const float* __restrict__ inp_b)
{
    const int tid = threadIdx.x;
    const int b   = tid & 63;
    const int jl  = tid >> 6;
    const int j   = blockIdx.x * 4 + jl;

    __shared__ float s_w[4][H_ + I_];
    // rows j..j+3 are contiguous: 1024 contiguous floats
    const float* wbase = inp_W + blockIdx.x * 4 * (H_ + I_);
    #pragma unroll
    for (int i = tid; i < 4 * (H_ + I_); i += 256) {
        s_w[i >> 8][i & 255] = wbase[i];
    }
    __syncthreads();

    float acc = inp_b[j];
    #pragma unroll 8
    for (int k = 0; k < H_ + I_; k++) {
        acc += s_w[jl][k] * g_xcatT[k * B_ + b];
    }
    g_xinT[j * B_ + b] = acc;
}

// ---------------------------------------------------------------------------
// K4/K5: one LSTM cell. grid = H_ blocks (one per h), 256 threads:
// b = tid&63, gate = tid>>6, j = gate*128 + h. Gate GEMV (K=256) as
// thread-per-output, then in-block activation.
// xT / hT: transposed inputs [k][b]. cPrev: layer slice of c0 (B,H).
// outH/outH2/outC: destinations (B,H layout). hT_out: optional transposed h.
// ---------------------------------------------------------------------------
__global__ __launch_bounds__(256)
void lstm_cell_kernel(const float* __restrict__ xT,
                      const float* __restrict__ hT,
                      const float* __restrict__ W_ih,
                      const float* __restrict__ W_hh,
                      const float* __restrict__ b_ih,
                      const float* __restrict__ b_hh,
                      const float* __restrict__ cPrev,
                      float* __restrict__ outH,
                      float* __restrict__ outH2,
                      float* __restrict__ outC,
                      float* __restrict__ hT_out)
{
    const int h    = blockIdx.x;
    const int tid  = threadIdx.x;
    const int b    = tid & 63;
    const int gate = tid >> 6;
    const int j    = gate * H_ + h;

    __shared__ float s_w[4][2 * H_];   // [gate][ W_ih row | W_hh row ]
    __shared__ float s_g[4][B_];

    #pragma unroll
    for (int i = tid; i < 4 * H_; i += 256) {
        const int g = i >> 7;
        const int k = i & 127;
        s_w[g][k]      = W_ih[(g * H_ + h) * H_ + k];
        s_w[g][H_ + k] = W_hh[(g * H_ + h) * H_ + k];
    }
    __syncthreads();

    float acc = b_ih[j] + b_hh[j];
    #pragma unroll 8
    for (int k = 0; k < H_; k++) {
        acc += s_w[gate][k] * xT[k * B_ + b];
    }
    #pragma unroll 8
    for (int k = 0; k < H_; k++) {
        acc += s_w[gate][H_ + k] * hT[k * B_ + b];
    }
    s_g[gate][b] = acc;
    __syncthreads();

    if (tid < B_) {
        const int bb = tid;
        const float gi = s_g[0][bb];
        const float gf = s_g[1][bb];
        const float gg = s_g[2][bb];
        const float go = s_g[3][bb];
        const float cp = cPrev[bb * H_ + h];
        const float cN = sigm(gf) * cp + sigm(gi) * tanhf(gg);
        const float hN = sigm(go) * tanhf(cN);
        outH[bb * H_ + h] = hN;
        if (outH2) outH2[bb * H_ + h] = hN;
        outC[bb * H_ + h] = cN;
        if (hT_out) hT_out[h * B_ + bb] = hN;
    }
}

extern "C" void kernel_launch(void* const* d_in, const int* in_sizes, int n_in,
                              void* d_out, int out_size) {
    const float* input  = (const float*)d_in[0];
    const float* h0     = (const float*)d_in[1];
    const float* c0     = (const float*)d_in[2];
    const float* enc    = (const float*)d_in[3];
    const float* attW   = (const float*)d_in[4];
    const float* attB   = (const float*)d_in[5];
    const float* inp_W  = (const float*)d_in[6];
    const float* inp_b  = (const float*)d_in[7];
    const float* W_ih0  = (const float*)d_in[8];
    const float* W_hh0  = (const float*)d_in[9];
    const float* b_ih0  = (const float*)d_in[10];
    const float* b_hh0  = (const float*)d_in[11];
    const float* W_ih1  = (const float*)d_in[12];
    const float* W_hh1  = (const float*)d_in[13];
    const float* b_ih1  = (const float*)d_in[14];
    const float* b_hh1  = (const float*)d_in[15];
    float* out = (float*)d_out;

    // out layout: [h2 (B,H)] [h1] [h2] [c1] [c2]
    float* out_y  = out + 0 * B_ * H_;
    float* out_h1 = out + 1 * B_ * H_;
    float* out_h2 = out + 2 * B_ * H_;
    float* out_c1 = out + 3 * B_ * H_;
    float* out_c2 = out + 4 * B_ * H_;

    float* xcatT; cudaGetSymbolAddress((void**)&xcatT, g_xcatT);
    float* xinT;  cudaGetSymbolAddress((void**)&xinT,  g_xinT);
    float* h1T;   cudaGetSymbolAddress((void**)&h1T,   g_h1T);
    float* h0T0;  cudaGetSymbolAddress((void**)&h0T0,  g_h0T0);
    float* h0T1;  cudaGetSymbolAddress((void**)&h0T1,  g_h0T1);

    dim3 grid1(CHUNKS, B_);
    attn_partial_kernel<<<grid1, 256>>>(enc, h0, c0, attW, attB);
    combine_kernel<<<B_, 256>>>(input, h0);
    xin_kernel<<<I_ / 4, 256>>>(inp_W, inp_b);
    // LSTM layer 0: x = xin, h = h0[0], c = c0[0] -> h1 (also transposed), c1
    lstm_cell_kernel<<<H_, 256>>>(xinT, h0T0, W_ih0, W_hh0, b_ih0, b_hh0,
                                  c0 + 0 * B_ * H_,
                                  out_h1, nullptr, out_c1, h1T);
    // LSTM layer 1: x = h1, h = h0[1], c = c0[1] -> h2 (y + h-stack), c2
    lstm_cell_kernel<<<H_, 256>>>(h1T, h0T1, W_ih1, W_hh1, b_ih1, b_hh1,
                                  c0 + 1 * B_ * H_,
                                  out_y, out_h2, out_c2, nullptr);
}

// round 5
// speedup vs baseline: 2.5255x; 1.2882x over previous
#include <cuda_runtime.h>
#include <cuda_bf16.h>
#include <math.h>

#define B_ 64
#define W_ 4096
#define H_ 128
#define I_ 128
#define CHUNKS 8
#define TPB (W_ / CHUNKS)
#define WARPS 8
#define ROWS_PER_WARP (TPB / WARPS)

__device__ float g_pm[B_ * CHUNKS];
__device__ float g_pl[B_ * CHUNKS];
__device__ float g_pacc[B_ * CHUNKS * H_];

// Transposed activations [k][b]
__device__ float g_xcatT[(H_ + I_) * B_];
__device__ float g_xinT[I_ * B_];
__device__ float g_h1T[H_ * B_];
__device__ float g_h0T0[H_ * B_];
__device__ float g_h0T1[H_ * B_];

__device__ __forceinline__ float warp_sum(float v) {
    #pragma unroll
    for (int o = 16; o; o >>= 1) v += __shfl_xor_sync(0xffffffffu, v, o);
    return v;
}

__device__ __forceinline__ float sigm(float x) { return 1.0f / (1.0f + expf(-x)); }

// ---------------------------------------------------------------------------
// Phase 1: fused score + online-softmax weighted accumulate (1 encoder pass).
// ---------------------------------------------------------------------------
__global__ __launch_bounds__(256, 4)
void attn_partial_kernel(const float* __restrict__ enc,
                         const float* __restrict__ h0,
                         const float* __restrict__ c0,
                         const float* __restrict__ attW,
                         const float* __restrict__ attB)
{
    const int c    = blockIdx.x;
    const int b    = blockIdx.y;
    const int tid  = threadIdx.x;
    const int warp = tid >> 5;
    const int lane = tid & 31;

    __shared__ float s_red[WARPS];
    __shared__ float s_bias;
    __shared__ float s_m[WARPS], s_l[WARPS];
    __shared__ float s_acc[WARPS][H_];

    float part = 0.f;
    if (tid < H_) {
        float hs = h0[(1 * B_ + b) * H_ + tid];
        float cs = c0[(1 * B_ + b) * H_ + tid];
        part = hs * cs * attW[H_ + tid];
    }
    part = warp_sum(part);
    if (lane == 0) s_red[warp] = part;
    __syncthreads();
    if (tid == 0) {
        float s = 0.f;
        #pragma unroll
        for (int w = 0; w < WARPS; w++) s += s_red[w];
        s_bias = s + attB[0];
    }
    __syncthreads();
    const float bias = s_bias;

    const float4 wa = *reinterpret_cast<const float4*>(attW + lane * 4);

    const int rowStart = c * TPB + warp * ROWS_PER_WARP;
    const float* encb = enc + (size_t)b * W_ * H_;

    float prevLogit;
    if (rowStart == 0) {
        prevLogit = 0.0f;
    } else {
        float4 v = *reinterpret_cast<const float4*>(
            encb + (size_t)(rowStart - 1) * H_ + lane * 4);
        float d = v.x * wa.x + v.y * wa.y + v.z * wa.z + v.w * wa.w;
        d = warp_sum(d);
        prevLogit = d + bias;
    }

    float m = -1e30f, l = 0.f;
    float ax = 0.f, ay = 0.f, az = 0.f, aw = 0.f;

    const float* rp = encb + (size_t)rowStart * H_ + lane * 4;
    #pragma unroll 4
    for (int r = 0; r < ROWS_PER_WARP; r++) {
        const float4 v = *reinterpret_cast<const float4*>(rp);
        rp += H_;
        float d = v.x * wa.x + v.y * wa.y + v.z * wa.z + v.w * wa.w;
        d = warp_sum(d);
        const float logit = prevLogit;
        prevLogit = d + bias;
        const float mNew = fmaxf(m, logit);
        const float corr = __expf(m - mNew);
        const float p    = __expf(logit - mNew);
        l  = l * corr + p;
        ax = ax * corr + p * v.x;
        ay = ay * corr + p * v.y;
        az = az * corr + p * v.z;
        aw = aw * corr + p * v.w;
        m = mNew;
    }

    if (lane == 0) { s_m[warp] = m; s_l[warp] = l; }
    s_acc[warp][lane * 4 + 0] = ax;
    s_acc[warp][lane * 4 + 1] = ay;
    s_acc[warp][lane * 4 + 2] = az;
    s_acc[warp][lane * 4 + 3] = aw;
    __syncthreads();

    if (tid < H_) {
        float M = s_m[0];
        #pragma unroll
        for (int w = 1; w < WARPS; w++) M = fmaxf(M, s_m[w]);
        float L = 0.f, A = 0.f;
        #pragma unroll
        for (int w = 0; w < WARPS; w++) {
            const float e = __expf(s_m[w] - M);
            L += s_l[w] * e;
            A += s_acc[w][tid] * e;
        }
        const int pi = b * CHUNKS + c;
        g_pacc[pi * H_ + tid] = A;
        if (tid == 0) { g_pm[pi] = M; g_pl[pi] = L; }
    }
}

// ---------------------------------------------------------------------------
// K2: combine chunk partials -> xcatT; transpose h0 states.
// ---------------------------------------------------------------------------
__global__ __launch_bounds__(256)
void combine_kernel(const float* __restrict__ input,
                    const float* __restrict__ h0)
{
    const int b = blockIdx.x;
    const int k = threadIdx.x;

    if (k < H_) {
        float M = g_pm[b * CHUNKS + 0];
        #pragma unroll
        for (int cc = 1; cc < CHUNKS; cc++) M = fmaxf(M, g_pm[b * CHUNKS + cc]);
        float L = 0.f, A = 0.f;
        #pragma unroll
        for (int cc = 0; cc < CHUNKS; cc++) {
            const float e = __expf(g_pm[b * CHUNKS + cc] - M);
            L += g_pl[b * CHUNKS + cc] * e;
            A += g_pacc[(b * CHUNKS + cc) * H_ + k] * e;
        }
        g_xcatT[k * B_ + b] = A / L;
        g_h0T0[k * B_ + b] = h0[(0 * B_ + b) * H_ + k];
        g_h0T1[k * B_ + b] = h0[(1 * B_ + b) * H_ + k];
    } else {
        g_xcatT[k * B_ + b] = input[b * I_ + (k - H_)];
    }
}

// ---------------------------------------------------------------------------
// K3: xin GEMV, K split in half across threads.
// grid = 64 blocks (2 j each), 256 threads: bits [5:0]=b, [6]=jl, [7]=khalf.
// ---------------------------------------------------------------------------
__global__ __launch_bounds__(256)
void xin_kernel(const float* __restrict__ inp_W,
                const float* __restrict__ inp_b)
{
    const int tid   = threadIdx.x;
    const int b     = tid & 63;
    const int jl    = (tid >> 6) & 1;
    const int khalf = tid >> 7;
    const int j     = blockIdx.x * 2 + jl;

    __shared__ float s_w[2][H_ + I_];
    __shared__ float s_part[2][2][B_];

    const float* wbase = inp_W + blockIdx.x * 2 * (H_ + I_);
    #pragma unroll
    for (int i = tid; i < 2 * (H_ + I_); i += 256) {
        s_w[i >> 8][i & 255] = wbase[i];
    }
    __syncthreads();

    const float* wp = &s_w[jl][khalf * 128];
    const float* ap = &g_xcatT[khalf * 128 * B_];
    float acc = (khalf == 0) ? inp_b[j] : 0.f;
    #pragma unroll
    for (int kk = 0; kk < 128; kk += 8) {
        float v0 = ap[(kk + 0) * B_ + b];
        float v1 = ap[(kk + 1) * B_ + b];
        float v2 = ap[(kk + 2) * B_ + b];
        float v3 = ap[(kk + 3) * B_ + b];
        float v4 = ap[(kk + 4) * B_ + b];
        float v5 = ap[(kk + 5) * B_ + b];
        float v6 = ap[(kk + 6) * B_ + b];
        float v7 = ap[(kk + 7) * B_ + b];
        acc = fmaf(wp[kk + 0], v0, acc);
        acc = fmaf(wp[kk + 1], v1, acc);
        acc = fmaf(wp[kk + 2], v2, acc);
        acc = fmaf(wp[kk + 3], v3, acc);
        acc = fmaf(wp[kk + 4], v4, acc);
        acc = fmaf(wp[kk + 5], v5, acc);
        acc = fmaf(wp[kk + 6], v6, acc);
        acc = fmaf(wp[kk + 7], v7, acc);
    }
    s_part[khalf][jl][b] = acc;
    __syncthreads();

    if (tid < 128) {
        const int jl2 = tid >> 6;
        const int bb  = tid & 63;
        g_xinT[(blockIdx.x * 2 + jl2) * B_ + bb] =
            s_part[0][jl2][bb] + s_part[1][jl2][bb];
    }
}

// ---------------------------------------------------------------------------
// K4/K5: LSTM cell. grid = H_ blocks (h), 512 threads:
// bits [5:0]=b, [7:6]=gate, [8]=khalf (0: x-part, 1: h-part).
// Each thread: 128-MAC chain with 8-deep explicit load batches.
// ---------------------------------------------------------------------------
__global__ __launch_bounds__(512)
void lstm_cell_kernel(const float* __restrict__ xT,
                      const float* __restrict__ hT,
                      const float* __restrict__ W_ih,
                      const float* __restrict__ W_hh,
                      const float* __restrict__ b_ih,
                      const float* __restrict__ b_hh,
                      const float* __restrict__ cPrev,
                      float* __restrict__ outH,
                      float* __restrict__ outH2,
                      float* __restrict__ outC,
                      float* __restrict__ hT_out)
{
    const int h     = blockIdx.x;
    const int tid   = threadIdx.x;
    const int b     = tid & 63;
    const int gate  = (tid >> 6) & 3;
    const int khalf = tid >> 8;
    const int j     = gate * H_ + h;

    __shared__ float s_w[4][2 * H_];     // [gate][ W_ih row | W_hh row ]
    __shared__ float s_part[2][4][B_];

    #pragma unroll
    for (int i = tid; i < 4 * 2 * H_; i += 512) {
        const int g = i >> 8;
        const int k = i & 255;
        s_w[g][k] = (k < H_) ? W_ih[(g * H_ + h) * H_ + k]
                             : W_hh[(g * H_ + h) * H_ + (k - H_)];
    }
    __syncthreads();

    const float* wp = &s_w[gate][khalf * H_];
    const float* ap = (khalf == 0) ? xT : hT;
    float acc = (khalf == 0) ? b_ih[j] : b_hh[j];
    #pragma unroll
    for (int kk = 0; kk < H_; kk += 8) {
        float v0 = ap[(kk + 0) * B_ + b];
        float v1 = ap[(kk + 1) * B_ + b];
        float v2 = ap[(kk + 2) * B_ + b];
        float v3 = ap[(kk + 3) * B_ + b];
        float v4 = ap[(kk + 4) * B_ + b];
        float v5 = ap[(kk + 5) * B_ + b];
        float v6 = ap[(kk + 6) * B_ + b];
        float v7 = ap[(kk + 7) * B_ + b];
        acc = fmaf(wp[kk + 0], v0, acc);
        acc = fmaf(wp[kk + 1], v1, acc);
        acc = fmaf(wp[kk + 2], v2, acc);
        acc = fmaf(wp[kk + 3], v3, acc);
        acc = fmaf(wp[kk + 4], v4, acc);
        acc = fmaf(wp[kk + 5], v5, acc);
        acc = fmaf(wp[kk + 6], v6, acc);
        acc = fmaf(wp[kk + 7], v7, acc);
    }
    s_part[khalf][gate][b] = acc;
    __syncthreads();

    if (tid < B_) {
        const int bb = tid;
        const float gi = s_part[0][0][bb] + s_part[1][0][bb];
        const float gf = s_part[0][1][bb] + s_part[1][1][bb];
        const float gg = s_part[0][2][bb] + s_part[1][2][bb];
        const float go = s_part[0][3][bb] + s_part[1][3][bb];
        const float cp = cPrev[bb * H_ + h];
        const float cN = sigm(gf) * cp + sigm(gi) * tanhf(gg);
        const float hN = sigm(go) * tanhf(cN);
        outH[bb * H_ + h] = hN;
        if (outH2) outH2[bb * H_ + h] = hN;
        outC[bb * H_ + h] = cN;
        if (hT_out) hT_out[h * B_ + bb] = hN;
    }
}

extern "C" void kernel_launch(void* const* d_in, const int* in_sizes, int n_in,
                              void* d_out, int out_size) {
    const float* input  = (const float*)d_in[0];
    const float* h0     = (const float*)d_in[1];
    const float* c0     = (const float*)d_in[2];
    const float* enc    = (const float*)d_in[3];
    const float* attW   = (const float*)d_in[4];
    const float* attB   = (const float*)d_in[5];
    const float* inp_W  = (const float*)d_in[6];
    const float* inp_b  = (const float*)d_in[7];
    const float* W_ih0  = (const float*)d_in[8];
    const float* W_hh0  = (const float*)d_in[9];
    const float* b_ih0  = (const float*)d_in[10];
    const float* b_hh0  = (const float*)d_in[11];
    const float* W_ih1  = (const float*)d_in[12];
    const float* W_hh1  = (const float*)d_in[13];
    const float* b_ih1  = (const float*)d_in[14];
    const float* b_hh1  = (const float*)d_in[15];
    float* out = (float*)d_out;

    float* out_y  = out + 0 * B_ * H_;
    float* out_h1 = out + 1 * B_ * H_;
    float* out_h2 = out + 2 * B_ * H_;
    float* out_c1 = out + 3 * B_ * H_;
    float* out_c2 = out + 4 * B_ * H_;

    float* xinT;  cudaGetSymbolAddress((void**)&xinT,  g_xinT);
    float* h1T;   cudaGetSymbolAddress((void**)&h1T,   g_h1T);
    float* h0T0;  cudaGetSymbolAddress((void**)&h0T0,  g_h0T0);
    float* h0T1;  cudaGetSymbolAddress((void**)&h0T1,  g_h0T1);

    dim3 grid1(CHUNKS, B_);
    attn_partial_kernel<<<grid1, 256>>>(enc, h0, c0, attW, attB);
    combine_kernel<<<B_, 256>>>(input, h0);
    xin_kernel<<<I_ / 2, 256>>>(inp_W, inp_b);
    lstm_cell_kernel<<<H_, 512>>>(xinT, h0T0, W_ih0, W_hh0, b_ih0, b_hh0,
                                  c0 + 0 * B_ * H_,
                                  out_h1, nullptr, out_c1, h1T);
    lstm_cell_kernel<<<H_, 512>>>(h1T, h0T1, W_ih1, W_hh1, b_ih1, b_hh1,
                                  c0 + 1 * B_ * H_,
                                  out_y, out_h2, out_c2, nullptr);
}